// round 2
// baseline (speedup 1.0000x reference)
#include <cuda_runtime.h>
#include <math.h>

#define NB   16
#define NT   1000
#define NF   512
#define NH   512
#define NSEQ 2000
#define MROWS (NB*NT)   /* 16000 */
#define DOUT  1024      /* 2H */

#define BM 64
#define BN 64
#define BK 16

// ---------------- scratch (device globals; no runtime allocation) ----------------
__device__ float g_Wpre[MROWS*DOUT];        // [b][t][n]  BN(x@[Wz;Wh]^T+b)  (65.5MB)
__device__ float g_H[NSEQ*NB*NH];           // [s][b][j]  all hidden states  (65.5MB)
__device__ float g_ln[MROWS*DOUT];          // layernorm output              (65.5MB)
__device__ float g_hbuf[8][2][2][NH];       // [group][parity][b][j]
__device__ int   g_arrv[8];                 // per-group arrival counters
__device__ float g_scale[DOUT];             // folded BN scale
__device__ float g_shift[DOUT];             // folded BN shift (incl. gemm bias)

// ---------------- setup: fold BN + bias, reset barriers ----------------
__global__ void setup_kernel(const float* __restrict__ bz, const float* __restrict__ bh,
                             const float* __restrict__ zg, const float* __restrict__ zb,
                             const float* __restrict__ zm, const float* __restrict__ zv,
                             const float* __restrict__ hg, const float* __restrict__ hb,
                             const float* __restrict__ hm, const float* __restrict__ hv)
{
    int n = blockIdx.x * blockDim.x + threadIdx.x;
    if (n < 512) {
        float sc = zg[n] * rsqrtf(zv[n] + 1e-5f);
        g_scale[n] = sc;
        g_shift[n] = (bz[n] - zm[n]) * sc + zb[n];
    } else if (n < 1024) {
        int m = n - 512;
        float sc = hg[m] * rsqrtf(hv[m] + 1e-5f);
        g_scale[n] = sc;
        g_shift[n] = (bh[m] - hm[m]) * sc + hb[m];
    }
    if (blockIdx.x == 0 && threadIdx.x < 8) g_arrv[threadIdx.x] = 0;
}

// ---------------- generic NT GEMM: C[M,N] = A[M,K] * Brow[n][K] ----------------
// MODE 0: val = acc*e0[n] + e1[n]     (BN fold epilogue)
// MODE 1: val = tanhf(acc + e0[n])    (projection epilogue)
template<int MODE>
__global__ __launch_bounds__(256)
void gemm_nt(const float* __restrict__ A,
             const float* __restrict__ B0, const float* __restrict__ B1, int nsplit,
             float* __restrict__ C, int M, int N, int K,
             const float* __restrict__ e0, const float* __restrict__ e1)
{
    __shared__ float As[BK][BM + 4];
    __shared__ float Bs[BK][BN + 4];

    const int m0 = blockIdx.x * BM;
    const int n0 = blockIdx.y * BN;
    const int tid = threadIdx.x;
    const int tx = tid & 15;        // n micro
    const int ty = tid >> 4;        // m micro

    const int lr = tid >> 2;        // 0..63 row within tile
    const int lc = (tid & 3) * 4;   // k start within k-tile

    float acc[4][4];
#pragma unroll
    for (int i = 0; i < 4; i++)
#pragma unroll
        for (int j = 0; j < 4; j++) acc[i][j] = 0.f;

    const int nrow = n0 + lr;
    const float* brow = (nrow < nsplit) ? (B0 + (size_t)nrow * K)
                                        : (B1 + (size_t)(nrow - nsplit) * K);
    const float* arow = A + (size_t)(m0 + lr) * K;

    for (int k0 = 0; k0 < K; k0 += BK) {
        float4 a4 = *(const float4*)(arow + k0 + lc);
        float4 b4 = *(const float4*)(brow + k0 + lc);
        As[lc + 0][lr] = a4.x; As[lc + 1][lr] = a4.y;
        As[lc + 2][lr] = a4.z; As[lc + 3][lr] = a4.w;
        Bs[lc + 0][lr] = b4.x; Bs[lc + 1][lr] = b4.y;
        Bs[lc + 2][lr] = b4.z; Bs[lc + 3][lr] = b4.w;
        __syncthreads();

#pragma unroll
        for (int k = 0; k < BK; k++) {
            float4 av = *(const float4*)&As[k][ty * 4];
            float4 bv = *(const float4*)&Bs[k][tx * 4];
            float a[4] = {av.x, av.y, av.z, av.w};
            float b[4] = {bv.x, bv.y, bv.z, bv.w};
#pragma unroll
            for (int i = 0; i < 4; i++)
#pragma unroll
                for (int j = 0; j < 4; j++)
                    acc[i][j] = fmaf(a[i], b[j], acc[i][j]);
        }
        __syncthreads();
    }

#pragma unroll
    for (int i = 0; i < 4; i++) {
        int m = m0 + ty * 4 + i;
#pragma unroll
        for (int j = 0; j < 4; j++) {
            int n = n0 + tx * 4 + j;
            float v = acc[i][j];
            if (MODE == 0) v = v * e0[n] + e1[n];
            else           v = tanhf(v + e0[n]);
            C[(size_t)m * N + n] = v;
        }
    }
}

// ---------------- persistent LiGRU recurrence ----------------
// grid = 128 CTAs: 8 groups x 16 CTAs. Group g owns batch rows {2g, 2g+1}.
// CTA c of a group owns j in [c*32, c*32+32). warp = k-slice (8 x 64), lane = j.
// U slice lives in registers: Uz[64] + Uh[64] per thread.
__global__ __launch_bounds__(256, 1)
void ligru_kernel(const float* __restrict__ U)
{
    const int g   = blockIdx.x >> 4;   // 0..7
    const int c   = blockIdx.x & 15;   // 0..15
    const int tid = threadIdx.x;
    const int w   = tid >> 5;          // 0..7  (k-slice)
    const int l   = tid & 31;          // 0..31 (j within slice)
    const int j   = c * 32 + l;        // 0..511
    const int kb  = w * 64;            // k base

    // load U slice into registers (one-time)
    float Uz[64], Uh[64];
    {
        const float4* uz4 = (const float4*)(U + (size_t)j * NH + kb);
        const float4* uh4 = (const float4*)(U + (size_t)(512 + j) * NH + kb);
#pragma unroll
        for (int i = 0; i < 16; i++) {
            float4 a = __ldg(uz4 + i);
            Uz[4*i+0] = a.x; Uz[4*i+1] = a.y; Uz[4*i+2] = a.z; Uz[4*i+3] = a.w;
            float4 b = __ldg(uh4 + i);
            Uh[4*i+0] = b.x; Uh[4*i+1] = b.y; Uh[4*i+2] = b.z; Uh[4*i+3] = b.w;
        }
    }

    __shared__ float hsm[2][NH];
    __shared__ float red[8][32][5];   // [warp][j][{az0,az1,ah0,ah1}] pad->5 for banks
    for (int i = tid; i < 2 * NH; i += 256) ((float*)hsm)[i] = 0.f;
    __syncthreads();

    // epilogue thread mapping (tid < 64): bo = local batch, jo = j within slice
    const int bo = (tid >> 5) & 1;
    const int jo = tid & 31;
    const int jg = c * 32 + jo;
    const int bglob = 2 * g + bo;

#pragma unroll 1
    for (int s = 0; s < NSEQ; s++) {
        // prefetch this step's gate pre-activations (hidden under dot compute)
        float wzv = 0.f, whv = 0.f;
        if (tid < 64) {
            int srcb, tt;
            if (s < NT) { srcb = bglob;          tt = s; }
            else        { srcb = NB - 1 - bglob; tt = s - NT; }
            const float* wp = g_Wpre + ((size_t)srcb * NT + tt) * DOUT;
            wzv = __ldg(wp + jg);
            whv = __ldg(wp + 512 + jg);
        }

        // partial dots over this warp's k-slice, both batches, both gates
        float az0 = 0.f, az1 = 0.f, ah0 = 0.f, ah1 = 0.f;
        {
            const float4* h0 = (const float4*)&hsm[0][kb];
            const float4* h1 = (const float4*)&hsm[1][kb];
#pragma unroll
            for (int q = 0; q < 16; q++) {
                float4 v0 = h0[q];
                az0 = fmaf(Uz[4*q+0], v0.x, az0); az0 = fmaf(Uz[4*q+1], v0.y, az0);
                az0 = fmaf(Uz[4*q+2], v0.z, az0); az0 = fmaf(Uz[4*q+3], v0.w, az0);
                ah0 = fmaf(Uh[4*q+0], v0.x, ah0); ah0 = fmaf(Uh[4*q+1], v0.y, ah0);
                ah0 = fmaf(Uh[4*q+2], v0.z, ah0); ah0 = fmaf(Uh[4*q+3], v0.w, ah0);
                float4 v1 = h1[q];
                az1 = fmaf(Uz[4*q+0], v1.x, az1); az1 = fmaf(Uz[4*q+1], v1.y, az1);
                az1 = fmaf(Uz[4*q+2], v1.z, az1); az1 = fmaf(Uz[4*q+3], v1.w, az1);
                ah1 = fmaf(Uh[4*q+0], v1.x, ah1); ah1 = fmaf(Uh[4*q+1], v1.y, ah1);
                ah1 = fmaf(Uh[4*q+2], v1.z, ah1); ah1 = fmaf(Uh[4*q+3], v1.w, ah1);
            }
        }
        red[w][l][0] = az0; red[w][l][1] = az1;
        red[w][l][2] = ah0; red[w][l][3] = ah1;
        __syncthreads();

        if (tid < 64) {
            float uz = 0.f, uh = 0.f;
#pragma unroll
            for (int ww = 0; ww < 8; ww++) {
                uz += red[ww][jo][bo];
                uh += red[ww][jo][2 + bo];
            }
            float zt = 1.f / (1.f + expf(-(wzv + uz)));
            float hc = fmaxf(whv + uh, 0.f);
            float ho = hsm[bo][jg];
            float hn = zt * ho + (1.f - zt) * hc;
            g_hbuf[g][(s + 1) & 1][bo][jg] = hn;
            g_H[((size_t)s * NB + bglob) * NH + jg] = hn;
            __threadfence();
        }
        __syncthreads();

        // group barrier: 16 arrivals per step (monotonic counter)
        if (tid == 0) {
            atomicAdd(&g_arrv[g], 1);
            const int target = 16 * (s + 1);
            volatile int* a = (volatile int*)&g_arrv[g];
            while (*a < target) { }
        }
        __syncthreads();

        // reload full h for the group (bypass L1: writes came from other SMs)
        {
            const float* hbp = &g_hbuf[g][(s + 1) & 1][0][0];
            for (int i = tid; i < 2 * NH; i += 256)
                ((float*)hsm)[i] = __ldcg(hbp + i);
        }
        __syncthreads();
    }
}

// ---------------- LayerNorm over gathered bidirectional output ----------------
__global__ __launch_bounds__(256)
void ln_kernel(const float* __restrict__ lng, const float* __restrict__ lnb)
{
    const int r = blockIdx.x;            // 0..15999 = b*1000 + t
    const int b = r / NT, t = r - b * NT;
    const int tid = threadIdx.x;

    const float* s0 = g_H + ((size_t)t * NB + b) * NH;                 // forward
    const float* s1 = g_H + ((size_t)(NT + t) * NB + (NB - 1 - b)) * NH; // backward

    float v0 = s0[tid], v1 = s0[tid + 256];
    float v2 = s1[tid], v3 = s1[tid + 256];

    float s  = v0 + v1 + v2 + v3;
    float sq = v0*v0 + v1*v1 + v2*v2 + v3*v3;

    for (int o = 16; o; o >>= 1) {
        s  += __shfl_down_sync(0xffffffffu, s,  o);
        sq += __shfl_down_sync(0xffffffffu, sq, o);
    }
    __shared__ float rs_[8], rq_[8];
    __shared__ float mu_s, rstd_s;
    if ((tid & 31) == 0) { rs_[tid >> 5] = s; rq_[tid >> 5] = sq; }
    __syncthreads();
    if (tid == 0) {
        float S = 0.f, Q = 0.f;
#pragma unroll
        for (int i = 0; i < 8; i++) { S += rs_[i]; Q += rq_[i]; }
        float mu = S * (1.f / 1024.f);
        float var = Q * (1.f / 1024.f) - mu * mu;
        mu_s = mu;
        rstd_s = rsqrtf(var + 1e-5f);
    }
    __syncthreads();
    const float mu = mu_s, rs = rstd_s;

    float* o = g_ln + (size_t)r * DOUT;
    o[tid]        = (v0 - mu) * rs * lng[tid]        + lnb[tid];
    o[tid + 256]  = (v1 - mu) * rs * lng[tid + 256]  + lnb[tid + 256];
    o[tid + 512]  = (v2 - mu) * rs * lng[tid + 512]  + lnb[tid + 512];
    o[tid + 768]  = (v3 - mu) * rs * lng[tid + 768]  + lnb[tid + 768];
}

// ---------------- x_len passthrough tail ----------------
__global__ void tail_kernel(const int* __restrict__ xl, float* __restrict__ out, int n)
{
    int i = threadIdx.x;
    if (i < n) out[(size_t)MROWS * DOUT + i] = (float)xl[i];
}

// ---------------- launch ----------------
extern "C" void kernel_launch(void* const* d_in, const int* in_sizes, int n_in,
                              void* d_out, int out_size)
{
    const float* x    = (const float*)d_in[0];
    const int*   xlen = (const int*)  d_in[1];
    const float* Wz   = (const float*)d_in[2];
    const float* bz   = (const float*)d_in[3];
    const float* Wh   = (const float*)d_in[4];
    const float* bh   = (const float*)d_in[5];
    const float* U    = (const float*)d_in[6];
    const float* zg   = (const float*)d_in[7];
    const float* zb   = (const float*)d_in[8];
    const float* zm   = (const float*)d_in[9];
    const float* zv   = (const float*)d_in[10];
    const float* hg   = (const float*)d_in[11];
    const float* hbb  = (const float*)d_in[12];
    const float* hm   = (const float*)d_in[13];
    const float* hv   = (const float*)d_in[14];
    const float* lng  = (const float*)d_in[15];
    const float* lnb  = (const float*)d_in[16];
    const float* pjW  = (const float*)d_in[17];
    const float* pjb  = (const float*)d_in[18];
    float* out = (float*)d_out;

    float *Wpre, *lnp, *scl, *shf;
    cudaGetSymbolAddress((void**)&Wpre, g_Wpre);
    cudaGetSymbolAddress((void**)&lnp,  g_ln);
    cudaGetSymbolAddress((void**)&scl,  g_scale);
    cudaGetSymbolAddress((void**)&shf,  g_shift);

    setup_kernel<<<4, 256>>>(bz, bh, zg, zb, zm, zv, hg, hbb, hm, hv);

    dim3 gg(MROWS / BM, DOUT / BN);
    gemm_nt<0><<<gg, 256>>>(x, Wz, Wh, 512, Wpre, MROWS, DOUT, NF, scl, shf);

    ligru_kernel<<<128, 256>>>(U);

    ln_kernel<<<MROWS, 256>>>(lng, lnb);

    gemm_nt<1><<<gg, 256>>>(lnp, pjW, pjW, DOUT, out, MROWS, DOUT, DOUT, pjb, pjb);

    int tail = out_size - MROWS * DOUT;
    if (tail > 0) tail_kernel<<<1, 32>>>(xlen, out, tail > NB ? NB : tail);
}

// round 3
// speedup vs baseline: 1.1723x; 1.1723x over previous
#include <cuda_runtime.h>
#include <math.h>

#define NB   16
#define NT   1000
#define NF   512
#define NH   512
#define NSEQ 2000
#define MROWS (NB*NT)   /* 16000 */
#define DOUT  1024      /* 2H */

#define GBM 128
#define GBN 128
#define GBK 16

typedef unsigned long long ull;

// ---------------- f32x2 packed helpers (sm_100+) ----------------
__device__ __forceinline__ ull f2pk(float lo, float hi) {
    ull r; asm("mov.b64 %0, {%1, %2};" : "=l"(r) : "f"(lo), "f"(hi)); return r;
}
__device__ __forceinline__ float2 f2unpk(ull v) {
    float2 r; asm("mov.b64 {%0, %1}, %2;" : "=f"(r.x), "=f"(r.y) : "l"(v)); return r;
}
__device__ __forceinline__ void fma2(ull& d, ull a, ull b) {
    asm("fma.rn.f32x2 %0, %1, %2, %0;" : "+l"(d) : "l"(a), "l"(b));
}

// ---------------- scratch (device globals; no runtime allocation) ----------------
__device__ float g_Wpre[MROWS*DOUT];        // [b][t][n]  BN(x@[Wz;Wh]^T+b)
__device__ float g_H[NSEQ*NB*NH];           // [s][b][j]  all hidden states
__device__ float g_ln[MROWS*DOUT];          // layernorm output
__device__ float g_hbuf[8][2][2][NH];       // [group][parity][b][j]
__device__ int   g_arrv[8];                 // per-group arrival counters
__device__ float g_scale[DOUT];             // folded BN scale
__device__ float g_shift[DOUT];             // folded BN shift (incl. gemm bias)

// ---------------- setup: fold BN + bias, reset barriers ----------------
__global__ void setup_kernel(const float* __restrict__ bz, const float* __restrict__ bh,
                             const float* __restrict__ zg, const float* __restrict__ zb,
                             const float* __restrict__ zm, const float* __restrict__ zv,
                             const float* __restrict__ hg, const float* __restrict__ hb,
                             const float* __restrict__ hm, const float* __restrict__ hv)
{
    int n = blockIdx.x * blockDim.x + threadIdx.x;
    if (n < 512) {
        float sc = zg[n] * rsqrtf(zv[n] + 1e-5f);
        g_scale[n] = sc;
        g_shift[n] = (bz[n] - zm[n]) * sc + zb[n];
    } else if (n < 1024) {
        int m = n - 512;
        float sc = hg[m] * rsqrtf(hv[m] + 1e-5f);
        g_scale[n] = sc;
        g_shift[n] = (bh[m] - hm[m]) * sc + hb[m];
    }
    if (blockIdx.x == 0 && threadIdx.x < 8) g_arrv[threadIdx.x] = 0;
}

// ---------------- 128x128x16 f32x2 GEMM: C[M,N] = A[M,K] * Brow[n][K] ----------------
// MODE 0: val = acc*e0[n] + e1[n]     (BN fold epilogue)
// MODE 1: val = tanhf(acc + e0[n])    (projection epilogue)
template<int MODE>
__global__ __launch_bounds__(256, 2)
void gemm_nt2(const float* __restrict__ A,
              const float* __restrict__ B0, const float* __restrict__ B1, int nsplit,
              float* __restrict__ C, int M, int N, int K,
              const float* __restrict__ e0, const float* __restrict__ e1)
{
    __shared__ float As[2][GBK][GBM + 4];
    __shared__ float Bs[2][GBK][GBN + 4];

    const int m0 = blockIdx.x * GBM;
    const int n0 = blockIdx.y * GBN;
    const int tid = threadIdx.x;

    // load mapping: each thread owns one row (of 128) and an 8-wide k half
    const int lr  = tid >> 1;          // 0..127
    const int lks = (tid & 1) * 8;     // 0 or 8

    // compute mapping: 16x16 thread grid, 4+4 split at distance 64 (conflict-free LDS.128)
    const int tx = tid & 15;           // n
    const int ty = tid >> 4;           // m

    const int nrow = n0 + lr;
    const float* brow = (nrow < nsplit) ? (B0 + (size_t)nrow * K)
                                        : (B1 + (size_t)(nrow - nsplit) * K);
    const float* arow = A + (size_t)(m0 + lr) * K;

    ull acc[2][4][2][2];               // [mblk][i][nblk][jpair]
#pragma unroll
    for (int a = 0; a < 2; a++)
#pragma unroll
        for (int i = 0; i < 4; i++)
#pragma unroll
            for (int b = 0; b < 2; b++) { acc[a][i][b][0] = 0ull; acc[a][i][b][1] = 0ull; }

    const int nt = K / GBK;
    float4 ga0, ga1, gb0, gb1;

    // preload tile 0
    ga0 = *(const float4*)(arow + lks);     ga1 = *(const float4*)(arow + lks + 4);
    gb0 = *(const float4*)(brow + lks);     gb1 = *(const float4*)(brow + lks + 4);
#pragma unroll
    for (int i = 0; i < 4; i++) {
        As[0][lks + i][lr]     = ((const float*)&ga0)[i];
        As[0][lks + 4 + i][lr] = ((const float*)&ga1)[i];
        Bs[0][lks + i][lr]     = ((const float*)&gb0)[i];
        Bs[0][lks + 4 + i][lr] = ((const float*)&gb1)[i];
    }
    __syncthreads();

    for (int t = 0; t < nt; t++) {
        const int cur = t & 1;
        if (t + 1 < nt) {
            const int k0 = (t + 1) * GBK;
            ga0 = *(const float4*)(arow + k0 + lks); ga1 = *(const float4*)(arow + k0 + lks + 4);
            gb0 = *(const float4*)(brow + k0 + lks); gb1 = *(const float4*)(brow + k0 + lks + 4);
        }

#pragma unroll
        for (int k = 0; k < GBK; k++) {
            float4 a0 = *(const float4*)&As[cur][k][ty * 4];
            float4 a1 = *(const float4*)&As[cur][k][64 + ty * 4];
            float4 b0 = *(const float4*)&Bs[cur][k][tx * 4];
            float4 b1 = *(const float4*)&Bs[cur][k][64 + tx * 4];
            ull bp[2][2] = { { f2pk(b0.x, b0.y), f2pk(b0.z, b0.w) },
                             { f2pk(b1.x, b1.y), f2pk(b1.z, b1.w) } };
            float am[2][4] = { { a0.x, a0.y, a0.z, a0.w },
                               { a1.x, a1.y, a1.z, a1.w } };
#pragma unroll
            for (int mb = 0; mb < 2; mb++)
#pragma unroll
                for (int i = 0; i < 4; i++) {
                    ull ap = f2pk(am[mb][i], am[mb][i]);
#pragma unroll
                    for (int nb = 0; nb < 2; nb++) {
                        fma2(acc[mb][i][nb][0], ap, bp[nb][0]);
                        fma2(acc[mb][i][nb][1], ap, bp[nb][1]);
                    }
                }
        }

        if (t + 1 < nt) {
            const int nxt = (t + 1) & 1;
#pragma unroll
            for (int i = 0; i < 4; i++) {
                As[nxt][lks + i][lr]     = ((const float*)&ga0)[i];
                As[nxt][lks + 4 + i][lr] = ((const float*)&ga1)[i];
                Bs[nxt][lks + i][lr]     = ((const float*)&gb0)[i];
                Bs[nxt][lks + 4 + i][lr] = ((const float*)&gb1)[i];
            }
            __syncthreads();
        }
    }

    // epilogue
#pragma unroll
    for (int mb = 0; mb < 2; mb++)
#pragma unroll
        for (int i = 0; i < 4; i++) {
            const int m = m0 + mb * 64 + ty * 4 + i;
#pragma unroll
            for (int nb = 0; nb < 2; nb++) {
                const int n = n0 + nb * 64 + tx * 4;
                float2 p0 = f2unpk(acc[mb][i][nb][0]);
                float2 p1 = f2unpk(acc[mb][i][nb][1]);
                float4 v = make_float4(p0.x, p0.y, p1.x, p1.y);
                if (MODE == 0) {
                    float4 s = *(const float4*)&e0[n];
                    float4 h = *(const float4*)&e1[n];
                    v.x = v.x * s.x + h.x; v.y = v.y * s.y + h.y;
                    v.z = v.z * s.z + h.z; v.w = v.w * s.w + h.w;
                } else {
                    float4 bb = *(const float4*)&e0[n];
                    v.x = tanhf(v.x + bb.x); v.y = tanhf(v.y + bb.y);
                    v.z = tanhf(v.z + bb.z); v.w = tanhf(v.w + bb.w);
                }
                *(float4*)&C[(size_t)m * N + n] = v;
            }
        }
}

// ---------------- persistent LiGRU recurrence (f32x2 dot) ----------------
// grid = 128 CTAs: 8 groups x 16 CTAs. Group g owns batch rows {2g, 2g+1}.
// CTA c of a group owns j in [c*32, c*32+32). warp = k-slice (8 x 64), lane = j.
__global__ __launch_bounds__(256, 1)
void ligru_kernel(const float* __restrict__ U)
{
    const int g   = blockIdx.x >> 4;   // 0..7
    const int c   = blockIdx.x & 15;   // 0..15
    const int tid = threadIdx.x;
    const int w   = tid >> 5;          // 0..7  (k-slice)
    const int l   = tid & 31;          // 0..31 (j within slice)
    const int j   = c * 32 + l;        // 0..511
    const int kb  = w * 64;            // k base

    // U slice in registers, pre-packed as f32x2 pairs (64 floats -> 32 ull per gate)
    ull Uz2[32], Uh2[32];
    {
        const ulonglong2* uz = (const ulonglong2*)(U + (size_t)j * NH + kb);
        const ulonglong2* uh = (const ulonglong2*)(U + (size_t)(512 + j) * NH + kb);
#pragma unroll
        for (int i = 0; i < 16; i++) {
            ulonglong2 a = uz[i]; Uz2[2*i] = a.x; Uz2[2*i+1] = a.y;
            ulonglong2 b = uh[i]; Uh2[2*i] = b.x; Uh2[2*i+1] = b.y;
        }
    }

    __shared__ float hsm[2][NH];
    __shared__ float red[8][32][5];   // [warp][j][{az0,az1,ah0,ah1}] pad->5
    for (int i = tid; i < 2 * NH; i += 256) ((float*)hsm)[i] = 0.f;
    __syncthreads();

    const int bo = (tid >> 5) & 1;
    const int jo = tid & 31;
    const int jg = c * 32 + jo;
    const int bglob = 2 * g + bo;

#pragma unroll 1
    for (int s = 0; s < NSEQ; s++) {
        // prefetch this step's gate pre-activations
        float wzv = 0.f, whv = 0.f;
        if (tid < 64) {
            int srcb, tt;
            if (s < NT) { srcb = bglob;          tt = s; }
            else        { srcb = NB - 1 - bglob; tt = s - NT; }
            const float* wp = g_Wpre + ((size_t)srcb * NT + tt) * DOUT;
            wzv = __ldg(wp + jg);
            whv = __ldg(wp + 512 + jg);
        }

        // partial dots over this warp's k-slice, both batches, both gates (f32x2)
        ull az0 = 0ull, az1 = 0ull, ah0 = 0ull, ah1 = 0ull;
        {
            const ulonglong2* h0 = (const ulonglong2*)&hsm[0][kb];
            const ulonglong2* h1 = (const ulonglong2*)&hsm[1][kb];
#pragma unroll
            for (int q = 0; q < 16; q++) {
                ulonglong2 v0 = h0[q];
                fma2(az0, Uz2[2*q], v0.x); fma2(az0, Uz2[2*q+1], v0.y);
                fma2(ah0, Uh2[2*q], v0.x); fma2(ah0, Uh2[2*q+1], v0.y);
                ulonglong2 v1 = h1[q];
                fma2(az1, Uz2[2*q], v1.x); fma2(az1, Uz2[2*q+1], v1.y);
                fma2(ah1, Uh2[2*q], v1.x); fma2(ah1, Uh2[2*q+1], v1.y);
            }
        }
        {
            float2 p;
            p = f2unpk(az0); red[w][l][0] = p.x + p.y;
            p = f2unpk(az1); red[w][l][1] = p.x + p.y;
            p = f2unpk(ah0); red[w][l][2] = p.x + p.y;
            p = f2unpk(ah1); red[w][l][3] = p.x + p.y;
        }
        __syncthreads();

        if (tid < 64) {
            float uz = 0.f, uh = 0.f;
#pragma unroll
            for (int ww = 0; ww < 8; ww++) {
                uz += red[ww][jo][bo];
                uh += red[ww][jo][2 + bo];
            }
            float zt = 1.f / (1.f + expf(-(wzv + uz)));
            float hc = fmaxf(whv + uh, 0.f);
            float ho = hsm[bo][jg];
            float hn = zt * ho + (1.f - zt) * hc;
            g_hbuf[g][(s + 1) & 1][bo][jg] = hn;
            g_H[((size_t)s * NB + bglob) * NH + jg] = hn;
            __threadfence();
        }
        __syncthreads();

        // group barrier: 16 arrivals per step (monotonic counter)
        if (tid == 0) {
            atomicAdd(&g_arrv[g], 1);
            const int target = 16 * (s + 1);
            volatile int* a = (volatile int*)&g_arrv[g];
            while (*a < target) { }
        }
        __syncthreads();

        // reload full h for the group (bypass L1)
        {
            const float* hbp = &g_hbuf[g][(s + 1) & 1][0][0];
            for (int i = tid; i < 2 * NH; i += 256)
                ((float*)hsm)[i] = __ldcg(hbp + i);
        }
        __syncthreads();
    }
}

// ---------------- LayerNorm over gathered bidirectional output ----------------
__global__ __launch_bounds__(256)
void ln_kernel(const float* __restrict__ lng, const float* __restrict__ lnb)
{
    const int r = blockIdx.x;            // 0..15999 = b*1000 + t
    const int b = r / NT, t = r - b * NT;
    const int tid = threadIdx.x;

    const float* s0 = g_H + ((size_t)t * NB + b) * NH;                   // forward
    const float* s1 = g_H + ((size_t)(NT + t) * NB + (NB - 1 - b)) * NH; // backward

    float v0 = s0[tid], v1 = s0[tid + 256];
    float v2 = s1[tid], v3 = s1[tid + 256];

    float s  = v0 + v1 + v2 + v3;
    float sq = v0*v0 + v1*v1 + v2*v2 + v3*v3;

    for (int o = 16; o; o >>= 1) {
        s  += __shfl_down_sync(0xffffffffu, s,  o);
        sq += __shfl_down_sync(0xffffffffu, sq, o);
    }
    __shared__ float rs_[8], rq_[8];
    __shared__ float mu_s, rstd_s;
    if ((tid & 31) == 0) { rs_[tid >> 5] = s; rq_[tid >> 5] = sq; }
    __syncthreads();
    if (tid == 0) {
        float S = 0.f, Q = 0.f;
#pragma unroll
        for (int i = 0; i < 8; i++) { S += rs_[i]; Q += rq_[i]; }
        float mu = S * (1.f / 1024.f);
        float var = Q * (1.f / 1024.f) - mu * mu;
        mu_s = mu;
        rstd_s = rsqrtf(var + 1e-5f);
    }
    __syncthreads();
    const float mu = mu_s, rs = rstd_s;

    float* o = g_ln + (size_t)r * DOUT;
    o[tid]        = (v0 - mu) * rs * lng[tid]        + lnb[tid];
    o[tid + 256]  = (v1 - mu) * rs * lng[tid + 256]  + lnb[tid + 256];
    o[tid + 512]  = (v2 - mu) * rs * lng[tid + 512]  + lnb[tid + 512];
    o[tid + 768]  = (v3 - mu) * rs * lng[tid + 768]  + lnb[tid + 768];
}

// ---------------- x_len passthrough tail ----------------
__global__ void tail_kernel(const int* __restrict__ xl, float* __restrict__ out, int n)
{
    int i = threadIdx.x;
    if (i < n) out[(size_t)MROWS * DOUT + i] = (float)xl[i];
}

// ---------------- launch ----------------
extern "C" void kernel_launch(void* const* d_in, const int* in_sizes, int n_in,
                              void* d_out, int out_size)
{
    const float* x    = (const float*)d_in[0];
    const int*   xlen = (const int*)  d_in[1];
    const float* Wz   = (const float*)d_in[2];
    const float* bz   = (const float*)d_in[3];
    const float* Wh   = (const float*)d_in[4];
    const float* bh   = (const float*)d_in[5];
    const float* U    = (const float*)d_in[6];
    const float* zg   = (const float*)d_in[7];
    const float* zb   = (const float*)d_in[8];
    const float* zm   = (const float*)d_in[9];
    const float* zv   = (const float*)d_in[10];
    const float* hg   = (const float*)d_in[11];
    const float* hbb  = (const float*)d_in[12];
    const float* hm   = (const float*)d_in[13];
    const float* hv   = (const float*)d_in[14];
    const float* lng  = (const float*)d_in[15];
    const float* lnb  = (const float*)d_in[16];
    const float* pjW  = (const float*)d_in[17];
    const float* pjb  = (const float*)d_in[18];
    float* out = (float*)d_out;

    float *Wpre, *lnp, *scl, *shf;
    cudaGetSymbolAddress((void**)&Wpre, g_Wpre);
    cudaGetSymbolAddress((void**)&lnp,  g_ln);
    cudaGetSymbolAddress((void**)&scl,  g_scale);
    cudaGetSymbolAddress((void**)&shf,  g_shift);

    setup_kernel<<<4, 256>>>(bz, bh, zg, zb, zm, zv, hg, hbb, hm, hv);

    dim3 gg(MROWS / GBM, DOUT / GBN);
    gemm_nt2<0><<<gg, 256>>>(x, Wz, Wh, 512, Wpre, MROWS, DOUT, NF, scl, shf);

    ligru_kernel<<<128, 256>>>(U);

    ln_kernel<<<MROWS, 256>>>(lng, lnb);

    gemm_nt2<1><<<gg, 256>>>(lnp, pjW, pjW, DOUT, out, MROWS, DOUT, DOUT, pjb, pjb);

    int tail = out_size - MROWS * DOUT;
    if (tail > 0) tail_kernel<<<1, 32>>>(xlen, out, tail > NB ? NB : tail);
}